// round 7
// baseline (speedup 1.0000x reference)
#include <cuda_runtime.h>

// out[p,:] = sum_{k in row p} PHI[k] * ctrl_pts[Jm[k],:]
// R6 validated model: 64M random 16B gathers = 64M L1tex wavefronts, L1 91.6%
// busy at 248us -> floor ~228us. R7 targets the idle 8%: 4 lanes/point,
// 8 points/warp, 16 front-batched __ldcg gathers per lane (MLP 16), SHFL and
// store overhead per point cut ~3x. Gather count unchanged (it's the floor).

#define MAX_CTRL 524288

__device__ __align__(16) float4 g_ctrl4[MAX_CTRL];   // 8 MB static scratch

__global__ __launch_bounds__(256)
void pack_ctrl_kernel(const float* __restrict__ ctrl, int n_ctrl)
{
    int i = blockIdx.x * blockDim.x + threadIdx.x;
    if (i < n_ctrl) {
        const float* c = ctrl + 3u * (unsigned)i;
        g_ctrl4[i] = make_float4(c[0], c[1], c[2], 0.0f);
    }
}

__global__ __launch_bounds__(256)
void thb_eval_packed_kernel(const float* __restrict__ phi,
                            const int*   __restrict__ jm,
                            const int*   __restrict__ cum,
                            float*       __restrict__ out,
                            int num_pts)
{
    const int tid  = blockIdx.x * blockDim.x + threadIdx.x;
    const int lane = threadIdx.x & 31;
    const int l4   = lane & 3;                       // lane within 4-lane group
    const int p    = (tid >> 5) * 8 + (lane >> 2);   // this group's point

    int start = 0, end = 0;
    if (p < num_pts) {
        start = (p == 0) ? 0 : cum[p - 1];
        end   = cum[p];
    }
    const int n = end - start;

    float sx = 0.f, sy = 0.f, sz = 0.f;

    if (n == 64 && ((start & 3) == 0)) {
        // lane covers entries [start + 16*l4, +16): 4 float4 + 4 int4 loads
        const float4* __restrict__ p4 = reinterpret_cast<const float4*>(phi + start);
        const int4*   __restrict__ j4 = reinterpret_cast<const int4*>(jm + start);

        float4 w[4];
        int4   j[4];
        #pragma unroll
        for (int i = 0; i < 4; i++) {
            w[i] = __ldcs(&p4[4 * l4 + i]);
            j[i] = __ldcs(&j4[4 * l4 + i]);
        }

        // 16 independent gathers, front-batched -> MLP 16
        float4 c[16];
        #pragma unroll
        for (int i = 0; i < 4; i++) {
            c[4*i + 0] = __ldcg(&g_ctrl4[j[i].x]);
            c[4*i + 1] = __ldcg(&g_ctrl4[j[i].y]);
            c[4*i + 2] = __ldcg(&g_ctrl4[j[i].z]);
            c[4*i + 3] = __ldcg(&g_ctrl4[j[i].w]);
        }

        #pragma unroll
        for (int i = 0; i < 4; i++) {
            const float wx = w[i].x, wy = w[i].y, wz = w[i].z, ww = w[i].w;
            sx = fmaf(wx, c[4*i+0].x, sx); sy = fmaf(wx, c[4*i+0].y, sy); sz = fmaf(wx, c[4*i+0].z, sz);
            sx = fmaf(wy, c[4*i+1].x, sx); sy = fmaf(wy, c[4*i+1].y, sy); sz = fmaf(wy, c[4*i+1].z, sz);
            sx = fmaf(wz, c[4*i+2].x, sx); sy = fmaf(wz, c[4*i+2].y, sy); sz = fmaf(wz, c[4*i+2].z, sz);
            sx = fmaf(ww, c[4*i+3].x, sx); sy = fmaf(ww, c[4*i+3].y, sy); sz = fmaf(ww, c[4*i+3].z, sz);
        }
    } else {
        for (int k = start + l4; k < end; k += 4) {
            const float w  = phi[k];
            const float4 cc = __ldcg(&g_ctrl4[jm[k]]);
            sx = fmaf(w, cc.x, sx);
            sy = fmaf(w, cc.y, sy);
            sz = fmaf(w, cc.z, sz);
        }
    }

    // butterfly reduce within each 4-lane group (2 steps x 3 vals = 6 SHFL/warp)
    #pragma unroll
    for (int off = 2; off > 0; off >>= 1) {
        sx += __shfl_xor_sync(0xFFFFFFFFu, sx, off);
        sy += __shfl_xor_sync(0xFFFFFFFFu, sy, off);
        sz += __shfl_xor_sync(0xFFFFFFFFu, sz, off);
    }

    if (l4 == 0 && p < num_pts) {
        const unsigned o = 3u * (unsigned)p;
        out[o + 0] = sx;
        out[o + 1] = sy;
        out[o + 2] = sz;
    }
}

// Generic fallback for oversized control tables (no packing possible).
__global__ __launch_bounds__(256)
void thb_eval_raw_kernel(const float* __restrict__ ctrl,
                         const float* __restrict__ phi,
                         const int*   __restrict__ jm,
                         const int*   __restrict__ cum,
                         float*       __restrict__ out,
                         int num_pts)
{
    const int warp = (int)((blockIdx.x * (unsigned)blockDim.x + threadIdx.x) >> 5);
    if (warp >= num_pts) return;
    const int lane = threadIdx.x & 31;

    const int start = (warp == 0) ? 0 : cum[warp - 1];
    const int end   = cum[warp];

    float sx = 0.f, sy = 0.f, sz = 0.f;
    for (int k = start + lane; k < end; k += 32) {
        const float w = phi[k];
        const float* c = ctrl + 3u * (unsigned)jm[k];
        sx = fmaf(w, c[0], sx);
        sy = fmaf(w, c[1], sy);
        sz = fmaf(w, c[2], sz);
    }

    #pragma unroll
    for (int off = 16; off > 0; off >>= 1) {
        sx += __shfl_xor_sync(0xFFFFFFFFu, sx, off);
        sy += __shfl_xor_sync(0xFFFFFFFFu, sy, off);
        sz += __shfl_xor_sync(0xFFFFFFFFu, sz, off);
    }

    if (lane == 0) {
        const unsigned o = 3u * (unsigned)warp;
        out[o + 0] = sx;
        out[o + 1] = sy;
        out[o + 2] = sz;
    }
}

extern "C" void kernel_launch(void* const* d_in, const int* in_sizes, int n_in,
                              void* d_out, int out_size)
{
    const float* ctrl = (const float*)d_in[0];   // [N_CTRL, 3] f32
    const float* phi  = (const float*)d_in[1];   // [TOTAL] f32
    const int*   jm   = (const int*)d_in[2];     // [TOTAL] i32
    const int*   cum  = (const int*)d_in[3];     // [P] i32 inclusive row ends
    float*       out  = (float*)d_out;           // [P, 3] f32

    const int n_ctrl  = in_sizes[0] / 3;
    const int num_pts = in_sizes[3];

    if (n_ctrl <= MAX_CTRL) {
        pack_ctrl_kernel<<<(n_ctrl + 255) / 256, 256>>>(ctrl, n_ctrl);
        const int blocks = (num_pts + 63) / 64;   // 8 points/warp, 8 warps/block
        thb_eval_packed_kernel<<<blocks, 256>>>(phi, jm, cum, out, num_pts);
    } else {
        const int threads = 256;
        const long long total_threads = (long long)num_pts * 32;
        const int blocks = (int)((total_threads + threads - 1) / threads);
        thb_eval_raw_kernel<<<blocks, threads>>>(ctrl, phi, jm, cum, out, num_pts);
    }
}

// round 8
// speedup vs baseline: 1.0447x; 1.0447x over previous
#include <cuda_runtime.h>

// out[p,:] = sum_{k in row p} PHI[k] * ctrl_pts[Jm[k],:]
// Validated model: 64M random 16B gathers = 64M L1tex wavefronts -> ~225us
// floor; R6 (8 lanes/pt, MLP 8, __ldcg) = 248us, L1 91.6%. R7 (MLP 16)
// regressed: ptxas won't hold 16 gathers in flight. R8 keeps the R6 body and
// makes the kernel PERSISTENT (912 CTAs, grid-stride over point-quads) to
// remove ~37 wave transitions + per-CTA MLP ramp (~20us of the gap).

#define MAX_CTRL 524288

__device__ __align__(16) float4 g_ctrl4[MAX_CTRL];   // 8 MB static scratch

__global__ __launch_bounds__(256)
void pack_ctrl_kernel(const float* __restrict__ ctrl, int n_ctrl)
{
    int i = blockIdx.x * blockDim.x + threadIdx.x;
    if (i < n_ctrl) {
        const float* c = ctrl + 3u * (unsigned)i;
        g_ctrl4[i] = make_float4(c[0], c[1], c[2], 0.0f);
    }
}

__global__ __launch_bounds__(256)
void thb_eval_packed_kernel(const float* __restrict__ phi,
                            const int*   __restrict__ jm,
                            const int*   __restrict__ cum,
                            float*       __restrict__ out,
                            int num_pts)
{
    const int lane   = threadIdx.x & 31;
    const int l8     = lane & 7;                      // lane within 8-lane group
    const int grp    = lane >> 3;                     // group 0..3 within warp
    const int warp0  = (int)((blockIdx.x * blockDim.x + threadIdx.x) >> 5);
    const int nwarps = (int)((gridDim.x * blockDim.x) >> 5);

    for (int pw0 = warp0 * 4; pw0 < num_pts; pw0 += nwarps * 4) {
        const int p = pw0 + grp;

        int start = 0, end = 0;
        if (p < num_pts) {
            start = (p == 0) ? 0 : cum[p - 1];
            end   = cum[p];
        }
        const int n = end - start;

        float sx = 0.f, sy = 0.f, sz = 0.f;

        if (n == 64 && ((start & 1) == 0)) {
            // lane covers entries [start + 8*l8, +8): two float4/int4 loads
            const float4* __restrict__ p4 = reinterpret_cast<const float4*>(phi + start);
            const int4*   __restrict__ j4 = reinterpret_cast<const int4*>(jm + start);
            const float4 w0 = __ldcs(&p4[2 * l8 + 0]);
            const float4 w1 = __ldcs(&p4[2 * l8 + 1]);
            const int4   j0 = __ldcs(&j4[2 * l8 + 0]);
            const int4   j1 = __ldcs(&j4[2 * l8 + 1]);

            // 8 independent gathers, L2-only -> MLP 8
            const float4 c0 = __ldcg(&g_ctrl4[j0.x]);
            const float4 c1 = __ldcg(&g_ctrl4[j0.y]);
            const float4 c2 = __ldcg(&g_ctrl4[j0.z]);
            const float4 c3 = __ldcg(&g_ctrl4[j0.w]);
            const float4 c4 = __ldcg(&g_ctrl4[j1.x]);
            const float4 c5 = __ldcg(&g_ctrl4[j1.y]);
            const float4 c6 = __ldcg(&g_ctrl4[j1.z]);
            const float4 c7 = __ldcg(&g_ctrl4[j1.w]);

            sx = fmaf(w0.x, c0.x, sx); sy = fmaf(w0.x, c0.y, sy); sz = fmaf(w0.x, c0.z, sz);
            sx = fmaf(w0.y, c1.x, sx); sy = fmaf(w0.y, c1.y, sy); sz = fmaf(w0.y, c1.z, sz);
            sx = fmaf(w0.z, c2.x, sx); sy = fmaf(w0.z, c2.y, sy); sz = fmaf(w0.z, c2.z, sz);
            sx = fmaf(w0.w, c3.x, sx); sy = fmaf(w0.w, c3.y, sy); sz = fmaf(w0.w, c3.z, sz);
            sx = fmaf(w1.x, c4.x, sx); sy = fmaf(w1.x, c4.y, sy); sz = fmaf(w1.x, c4.z, sz);
            sx = fmaf(w1.y, c5.x, sx); sy = fmaf(w1.y, c5.y, sy); sz = fmaf(w1.y, c5.z, sz);
            sx = fmaf(w1.z, c6.x, sx); sy = fmaf(w1.z, c6.y, sy); sz = fmaf(w1.z, c6.z, sz);
            sx = fmaf(w1.w, c7.x, sx); sy = fmaf(w1.w, c7.y, sy); sz = fmaf(w1.w, c7.z, sz);
        } else {
            for (int k = start + l8; k < end; k += 8) {
                const float w   = phi[k];
                const float4 cc = __ldcg(&g_ctrl4[jm[k]]);
                sx = fmaf(w, cc.x, sx);
                sy = fmaf(w, cc.y, sy);
                sz = fmaf(w, cc.z, sz);
            }
        }

        // butterfly reduce within each 8-lane group
        #pragma unroll
        for (int off = 4; off > 0; off >>= 1) {
            sx += __shfl_xor_sync(0xFFFFFFFFu, sx, off);
            sy += __shfl_xor_sync(0xFFFFFFFFu, sy, off);
            sz += __shfl_xor_sync(0xFFFFFFFFu, sz, off);
        }

        if (l8 == 0 && p < num_pts) {
            const unsigned o = 3u * (unsigned)p;
            out[o + 0] = sx;
            out[o + 1] = sy;
            out[o + 2] = sz;
        }
    }
}

// Generic fallback for oversized control tables (no packing possible).
__global__ __launch_bounds__(256)
void thb_eval_raw_kernel(const float* __restrict__ ctrl,
                         const float* __restrict__ phi,
                         const int*   __restrict__ jm,
                         const int*   __restrict__ cum,
                         float*       __restrict__ out,
                         int num_pts)
{
    const int warp = (int)((blockIdx.x * (unsigned)blockDim.x + threadIdx.x) >> 5);
    if (warp >= num_pts) return;
    const int lane = threadIdx.x & 31;

    const int start = (warp == 0) ? 0 : cum[warp - 1];
    const int end   = cum[warp];

    float sx = 0.f, sy = 0.f, sz = 0.f;
    for (int k = start + lane; k < end; k += 32) {
        const float w = phi[k];
        const float* c = ctrl + 3u * (unsigned)jm[k];
        sx = fmaf(w, c[0], sx);
        sy = fmaf(w, c[1], sy);
        sz = fmaf(w, c[2], sz);
    }

    #pragma unroll
    for (int off = 16; off > 0; off >>= 1) {
        sx += __shfl_xor_sync(0xFFFFFFFFu, sx, off);
        sy += __shfl_xor_sync(0xFFFFFFFFu, sy, off);
        sz += __shfl_xor_sync(0xFFFFFFFFu, sz, off);
    }

    if (lane == 0) {
        const unsigned o = 3u * (unsigned)warp;
        out[o + 0] = sx;
        out[o + 1] = sy;
        out[o + 2] = sz;
    }
}

extern "C" void kernel_launch(void* const* d_in, const int* in_sizes, int n_in,
                              void* d_out, int out_size)
{
    const float* ctrl = (const float*)d_in[0];   // [N_CTRL, 3] f32
    const float* phi  = (const float*)d_in[1];   // [TOTAL] f32
    const int*   jm   = (const int*)d_in[2];     // [TOTAL] i32
    const int*   cum  = (const int*)d_in[3];     // [P] i32 inclusive row ends
    float*       out  = (float*)d_out;           // [P, 3] f32

    const int n_ctrl  = in_sizes[0] / 3;
    const int num_pts = in_sizes[3];

    if (n_ctrl <= MAX_CTRL) {
        pack_ctrl_kernel<<<(n_ctrl + 255) / 256, 256>>>(ctrl, n_ctrl);
        // Persistent: ~one full wave (152 SMs x 6 CTAs), grid-stride inside.
        int blocks = 152 * 6;
        const int max_blocks = (num_pts + 31) / 32;
        if (blocks > max_blocks) blocks = max_blocks;
        thb_eval_packed_kernel<<<blocks, 256>>>(phi, jm, cum, out, num_pts);
    } else {
        const int threads = 256;
        const long long total_threads = (long long)num_pts * 32;
        const int blocks = (int)((total_threads + threads - 1) / threads);
        thb_eval_raw_kernel<<<blocks, threads>>>(ctrl, phi, jm, cum, out, num_pts);
    }
}

// round 9
// speedup vs baseline: 1.1005x; 1.0534x over previous
#include <cuda_runtime.h>

// out[p,:] = sum_{k in row p} PHI[k] * ctrl_pts[Jm[k],:]
// Validated: 64M random 16B gathers = 64M L1tex wavefronts (~225us floor);
// best = R6 (8 lanes/pt, 4 pts/warp, MLP 8, __ldcg, natural occupancy) at
// 248us. R9 = R6 + instruction-contiguous streaming loads ONLY (p4[l8],
// p4[l8+8]): each LDG.128 covers full 128B lines per 8-lane group, halving
// streaming wavefronts (8 -> 4 per point, ~12us). Previously this change was
// only ever tested bundled with regressions (R4 store-packing / R5 reg cap).

#define MAX_CTRL 524288

__device__ __align__(16) float4 g_ctrl4[MAX_CTRL];   // 8 MB static scratch

__global__ __launch_bounds__(256)
void pack_ctrl_kernel(const float* __restrict__ ctrl, int n_ctrl)
{
    int i = blockIdx.x * blockDim.x + threadIdx.x;
    if (i < n_ctrl) {
        const float* c = ctrl + 3u * (unsigned)i;
        g_ctrl4[i] = make_float4(c[0], c[1], c[2], 0.0f);
    }
}

__global__ __launch_bounds__(256)
void thb_eval_packed_kernel(const float* __restrict__ phi,
                            const int*   __restrict__ jm,
                            const int*   __restrict__ cum,
                            float*       __restrict__ out,
                            int num_pts)
{
    const int tid  = blockIdx.x * blockDim.x + threadIdx.x;
    const int lane = threadIdx.x & 31;
    const int l8   = lane & 7;                       // lane within 8-lane group
    const int p    = (tid >> 5) * 4 + (lane >> 3);   // this group's point

    int start = 0, end = 0;
    if (p < num_pts) {
        start = (p == 0) ? 0 : __ldg(&cum[p - 1]);
        end   = __ldg(&cum[p]);
    }
    const int n = end - start;

    float sx = 0.f, sy = 0.f, sz = 0.f;

    if (n == 64 && ((start & 3) == 0)) {
        // Instruction-contiguous streaming: load i covers row entries
        // [32*i + 4*l8, +4), so each LDG.128 reads whole 128B lines across
        // the 8-lane group (1 wf per instruction per group).
        const float4* __restrict__ p4 = reinterpret_cast<const float4*>(phi + start);
        const int4*   __restrict__ j4 = reinterpret_cast<const int4*>(jm + start);
        const float4 w0 = __ldcs(&p4[l8]);
        const float4 w1 = __ldcs(&p4[l8 + 8]);
        const int4   j0 = __ldcs(&j4[l8]);
        const int4   j1 = __ldcs(&j4[l8 + 8]);

        // 8 independent gathers, L2-only (no L1 allocation) -> MLP 8
        const float4 c0 = __ldcg(&g_ctrl4[j0.x]);
        const float4 c1 = __ldcg(&g_ctrl4[j0.y]);
        const float4 c2 = __ldcg(&g_ctrl4[j0.z]);
        const float4 c3 = __ldcg(&g_ctrl4[j0.w]);
        const float4 c4 = __ldcg(&g_ctrl4[j1.x]);
        const float4 c5 = __ldcg(&g_ctrl4[j1.y]);
        const float4 c6 = __ldcg(&g_ctrl4[j1.z]);
        const float4 c7 = __ldcg(&g_ctrl4[j1.w]);

        sx = fmaf(w0.x, c0.x, sx); sy = fmaf(w0.x, c0.y, sy); sz = fmaf(w0.x, c0.z, sz);
        sx = fmaf(w0.y, c1.x, sx); sy = fmaf(w0.y, c1.y, sy); sz = fmaf(w0.y, c1.z, sz);
        sx = fmaf(w0.z, c2.x, sx); sy = fmaf(w0.z, c2.y, sy); sz = fmaf(w0.z, c2.z, sz);
        sx = fmaf(w0.w, c3.x, sx); sy = fmaf(w0.w, c3.y, sy); sz = fmaf(w0.w, c3.z, sz);
        sx = fmaf(w1.x, c4.x, sx); sy = fmaf(w1.x, c4.y, sy); sz = fmaf(w1.x, c4.z, sz);
        sx = fmaf(w1.y, c5.x, sx); sy = fmaf(w1.y, c5.y, sy); sz = fmaf(w1.y, c5.z, sz);
        sx = fmaf(w1.z, c6.x, sx); sy = fmaf(w1.z, c6.y, sy); sz = fmaf(w1.z, c6.z, sz);
        sx = fmaf(w1.w, c7.x, sx); sy = fmaf(w1.w, c7.y, sy); sz = fmaf(w1.w, c7.z, sz);
    } else {
        for (int k = start + l8; k < end; k += 8) {
            const float w   = phi[k];
            const float4 cc = __ldcg(&g_ctrl4[jm[k]]);
            sx = fmaf(w, cc.x, sx);
            sy = fmaf(w, cc.y, sy);
            sz = fmaf(w, cc.z, sz);
        }
    }

    // butterfly reduce within each 8-lane group
    #pragma unroll
    for (int off = 4; off > 0; off >>= 1) {
        sx += __shfl_xor_sync(0xFFFFFFFFu, sx, off);
        sy += __shfl_xor_sync(0xFFFFFFFFu, sy, off);
        sz += __shfl_xor_sync(0xFFFFFFFFu, sz, off);
    }

    if (l8 == 0 && p < num_pts) {
        const unsigned o = 3u * (unsigned)p;
        out[o + 0] = sx;
        out[o + 1] = sy;
        out[o + 2] = sz;
    }
}

// Generic fallback for oversized control tables (no packing possible).
__global__ __launch_bounds__(256)
void thb_eval_raw_kernel(const float* __restrict__ ctrl,
                         const float* __restrict__ phi,
                         const int*   __restrict__ jm,
                         const int*   __restrict__ cum,
                         float*       __restrict__ out,
                         int num_pts)
{
    const int warp = (int)((blockIdx.x * (unsigned)blockDim.x + threadIdx.x) >> 5);
    if (warp >= num_pts) return;
    const int lane = threadIdx.x & 31;

    const int start = (warp == 0) ? 0 : cum[warp - 1];
    const int end   = cum[warp];

    float sx = 0.f, sy = 0.f, sz = 0.f;
    for (int k = start + lane; k < end; k += 32) {
        const float w = phi[k];
        const float* c = ctrl + 3u * (unsigned)jm[k];
        sx = fmaf(w, c[0], sx);
        sy = fmaf(w, c[1], sy);
        sz = fmaf(w, c[2], sz);
    }

    #pragma unroll
    for (int off = 16; off > 0; off >>= 1) {
        sx += __shfl_xor_sync(0xFFFFFFFFu, sx, off);
        sy += __shfl_xor_sync(0xFFFFFFFFu, sy, off);
        sz += __shfl_xor_sync(0xFFFFFFFFu, sz, off);
    }

    if (lane == 0) {
        const unsigned o = 3u * (unsigned)warp;
        out[o + 0] = sx;
        out[o + 1] = sy;
        out[o + 2] = sz;
    }
}

extern "C" void kernel_launch(void* const* d_in, const int* in_sizes, int n_in,
                              void* d_out, int out_size)
{
    const float* ctrl = (const float*)d_in[0];   // [N_CTRL, 3] f32
    const float* phi  = (const float*)d_in[1];   // [TOTAL] f32
    const int*   jm   = (const int*)d_in[2];     // [TOTAL] i32
    const int*   cum  = (const int*)d_in[3];     // [P] i32 inclusive row ends
    float*       out  = (float*)d_out;           // [P, 3] f32

    const int n_ctrl  = in_sizes[0] / 3;
    const int num_pts = in_sizes[3];

    if (n_ctrl <= MAX_CTRL) {
        pack_ctrl_kernel<<<(n_ctrl + 255) / 256, 256>>>(ctrl, n_ctrl);
        const int blocks = (num_pts + 31) / 32;   // 4 points/warp, 8 warps/block
        thb_eval_packed_kernel<<<blocks, 256>>>(phi, jm, cum, out, num_pts);
    } else {
        const int threads = 256;
        const long long total_threads = (long long)num_pts * 32;
        const int blocks = (int)((total_threads + threads - 1) / threads);
        thb_eval_raw_kernel<<<blocks, threads>>>(ctrl, phi, jm, cum, out, num_pts);
    }
}

// round 10
// speedup vs baseline: 1.1081x; 1.0069x over previous
#include <cuda_runtime.h>

// out[p,:] = sum_{k in row p} PHI[k] * ctrl_pts[Jm[k],:]
// Converged model: 64M random 16B gathers = 64M L1tex wavefronts; at 247us
// with L1 92% busy we are AT the wavefront floor (432K cyc/SM). R10 = R9 body
// unchanged, block 256 -> 128: finer CTA granularity (65536 CTAs), ~52
// resident warps/SM at the same 38 regs, smaller tail-wave imbalance.

#define MAX_CTRL 524288

__device__ __align__(16) float4 g_ctrl4[MAX_CTRL];   // 8 MB static scratch

__global__ __launch_bounds__(256)
void pack_ctrl_kernel(const float* __restrict__ ctrl, int n_ctrl)
{
    int i = blockIdx.x * blockDim.x + threadIdx.x;
    if (i < n_ctrl) {
        const float* c = ctrl + 3u * (unsigned)i;
        g_ctrl4[i] = make_float4(c[0], c[1], c[2], 0.0f);
    }
}

__global__ __launch_bounds__(128)
void thb_eval_packed_kernel(const float* __restrict__ phi,
                            const int*   __restrict__ jm,
                            const int*   __restrict__ cum,
                            float*       __restrict__ out,
                            int num_pts)
{
    const int tid  = blockIdx.x * blockDim.x + threadIdx.x;
    const int lane = threadIdx.x & 31;
    const int l8   = lane & 7;                       // lane within 8-lane group
    const int p    = (tid >> 5) * 4 + (lane >> 3);   // this group's point

    int start = 0, end = 0;
    if (p < num_pts) {
        start = (p == 0) ? 0 : __ldg(&cum[p - 1]);
        end   = __ldg(&cum[p]);
    }
    const int n = end - start;

    float sx = 0.f, sy = 0.f, sz = 0.f;

    if (n == 64 && ((start & 3) == 0)) {
        // Instruction-contiguous streaming: load i covers row entries
        // [32*i + 4*l8, +4), so each LDG.128 reads whole 128B lines across
        // the 8-lane group.
        const float4* __restrict__ p4 = reinterpret_cast<const float4*>(phi + start);
        const int4*   __restrict__ j4 = reinterpret_cast<const int4*>(jm + start);
        const float4 w0 = __ldcs(&p4[l8]);
        const float4 w1 = __ldcs(&p4[l8 + 8]);
        const int4   j0 = __ldcs(&j4[l8]);
        const int4   j1 = __ldcs(&j4[l8 + 8]);

        // 8 independent gathers, L2-only (no L1 allocation) -> MLP 8
        const float4 c0 = __ldcg(&g_ctrl4[j0.x]);
        const float4 c1 = __ldcg(&g_ctrl4[j0.y]);
        const float4 c2 = __ldcg(&g_ctrl4[j0.z]);
        const float4 c3 = __ldcg(&g_ctrl4[j0.w]);
        const float4 c4 = __ldcg(&g_ctrl4[j1.x]);
        const float4 c5 = __ldcg(&g_ctrl4[j1.y]);
        const float4 c6 = __ldcg(&g_ctrl4[j1.z]);
        const float4 c7 = __ldcg(&g_ctrl4[j1.w]);

        sx = fmaf(w0.x, c0.x, sx); sy = fmaf(w0.x, c0.y, sy); sz = fmaf(w0.x, c0.z, sz);
        sx = fmaf(w0.y, c1.x, sx); sy = fmaf(w0.y, c1.y, sy); sz = fmaf(w0.y, c1.z, sz);
        sx = fmaf(w0.z, c2.x, sx); sy = fmaf(w0.z, c2.y, sy); sz = fmaf(w0.z, c2.z, sz);
        sx = fmaf(w0.w, c3.x, sx); sy = fmaf(w0.w, c3.y, sy); sz = fmaf(w0.w, c3.z, sz);
        sx = fmaf(w1.x, c4.x, sx); sy = fmaf(w1.x, c4.y, sy); sz = fmaf(w1.x, c4.z, sz);
        sx = fmaf(w1.y, c5.x, sx); sy = fmaf(w1.y, c5.y, sy); sz = fmaf(w1.y, c5.z, sz);
        sx = fmaf(w1.z, c6.x, sx); sy = fmaf(w1.z, c6.y, sy); sz = fmaf(w1.z, c6.z, sz);
        sx = fmaf(w1.w, c7.x, sx); sy = fmaf(w1.w, c7.y, sy); sz = fmaf(w1.w, c7.z, sz);
    } else {
        for (int k = start + l8; k < end; k += 8) {
            const float w   = phi[k];
            const float4 cc = __ldcg(&g_ctrl4[jm[k]]);
            sx = fmaf(w, cc.x, sx);
            sy = fmaf(w, cc.y, sy);
            sz = fmaf(w, cc.z, sz);
        }
    }

    // butterfly reduce within each 8-lane group
    #pragma unroll
    for (int off = 4; off > 0; off >>= 1) {
        sx += __shfl_xor_sync(0xFFFFFFFFu, sx, off);
        sy += __shfl_xor_sync(0xFFFFFFFFu, sy, off);
        sz += __shfl_xor_sync(0xFFFFFFFFu, sz, off);
    }

    if (l8 == 0 && p < num_pts) {
        const unsigned o = 3u * (unsigned)p;
        out[o + 0] = sx;
        out[o + 1] = sy;
        out[o + 2] = sz;
    }
}

// Generic fallback for oversized control tables (no packing possible).
__global__ __launch_bounds__(256)
void thb_eval_raw_kernel(const float* __restrict__ ctrl,
                         const float* __restrict__ phi,
                         const int*   __restrict__ jm,
                         const int*   __restrict__ cum,
                         float*       __restrict__ out,
                         int num_pts)
{
    const int warp = (int)((blockIdx.x * (unsigned)blockDim.x + threadIdx.x) >> 5);
    if (warp >= num_pts) return;
    const int lane = threadIdx.x & 31;

    const int start = (warp == 0) ? 0 : cum[warp - 1];
    const int end   = cum[warp];

    float sx = 0.f, sy = 0.f, sz = 0.f;
    for (int k = start + lane; k < end; k += 32) {
        const float w = phi[k];
        const float* c = ctrl + 3u * (unsigned)jm[k];
        sx = fmaf(w, c[0], sx);
        sy = fmaf(w, c[1], sy);
        sz = fmaf(w, c[2], sz);
    }

    #pragma unroll
    for (int off = 16; off > 0; off >>= 1) {
        sx += __shfl_xor_sync(0xFFFFFFFFu, sx, off);
        sy += __shfl_xor_sync(0xFFFFFFFFu, sy, off);
        sz += __shfl_xor_sync(0xFFFFFFFFu, sz, off);
    }

    if (lane == 0) {
        const unsigned o = 3u * (unsigned)warp;
        out[o + 0] = sx;
        out[o + 1] = sy;
        out[o + 2] = sz;
    }
}

extern "C" void kernel_launch(void* const* d_in, const int* in_sizes, int n_in,
                              void* d_out, int out_size)
{
    const float* ctrl = (const float*)d_in[0];   // [N_CTRL, 3] f32
    const float* phi  = (const float*)d_in[1];   // [TOTAL] f32
    const int*   jm   = (const int*)d_in[2];     // [TOTAL] i32
    const int*   cum  = (const int*)d_in[3];     // [P] i32 inclusive row ends
    float*       out  = (float*)d_out;           // [P, 3] f32

    const int n_ctrl  = in_sizes[0] / 3;
    const int num_pts = in_sizes[3];

    if (n_ctrl <= MAX_CTRL) {
        pack_ctrl_kernel<<<(n_ctrl + 255) / 256, 256>>>(ctrl, n_ctrl);
        // 4 points/warp, 4 warps/block -> 16 points per block
        const int blocks = (num_pts + 15) / 16;
        thb_eval_packed_kernel<<<blocks, 128>>>(phi, jm, cum, out, num_pts);
    } else {
        const int threads = 256;
        const long long total_threads = (long long)num_pts * 32;
        const int blocks = (int)((total_threads + threads - 1) / threads);
        thb_eval_raw_kernel<<<blocks, threads>>>(ctrl, phi, jm, cum, out, num_pts);
    }
}